// round 1
// baseline (speedup 1.0000x reference)
#include <cuda_runtime.h>
#include <math.h>

#define N_RAYS   32768
#define S_USED   115        // only samples 0..114 contribute
#define GD       128        // grid dim
#define NCH      27         // 3 channels x 9 SH coeffs

__global__ __launch_bounds__(128, 8)
void rf_render_kernel(const float* __restrict__ xin,
                      const float* __restrict__ din,
                      const float* __restrict__ tminp,
                      const float* __restrict__ tmaxp,
                      const float* __restrict__ grid,
                      const float* __restrict__ opacity,
                      float* __restrict__ out)
{
    __shared__ float coef[S_USED][29];   // [sample][27 sh-weighted coeffs, 27=op]
    __shared__ float shs[9];
    __shared__ float wsum[4];
    __shared__ float red[4][3];

    const int ray  = blockIdx.x;
    const int tid  = threadIdx.x;
    const int lane = tid & 31;
    const int warp = tid >> 5;

    const float dx = din[ray*3+0];
    const float dy = din[ray*3+1];
    const float dz = din[ray*3+2];
    const float ox = xin[ray*3+0];
    const float oy = xin[ray*3+1];
    const float oz = xin[ray*3+2];
    const float t0 = tminp[ray];
    const float t1 = tmaxp[ray];
    const float range = t1 - t0;

    if (tid < 9) {
        float v = 0.f;
        switch (tid) {
            case 0: v = 0.28209479177387814f; break;
            case 1: v = -0.4886025119029199f * dy; break;
            case 2: v =  0.4886025119029199f * dz; break;
            case 3: v = -0.4886025119029199f * dx; break;
            case 4: v =  1.0925484305920792f * dx * dy; break;
            case 5: v = -1.0925484305920792f * dy * dz; break;
            case 6: v =  0.31539156525252005f * (2.f*dz*dz - dx*dx - dy*dy); break;
            case 7: v = -1.0925484305920792f * dx * dz; break;
            case 8: v =  0.5462742152960396f * (dx*dx - dy*dy); break;
        }
        shs[tid] = v;
    }
    __syncthreads();

    // per-lane SH multiplier (lanes 0..26 map to channel c=lane/9, basis b=lane%9)
    const float mysh = (lane < 27) ? shs[lane % 9] : 1.f;

    // ---- phase 1: warp-per-sample trilerp gather (channel-coalesced) ----
    for (int s = warp; s < S_USED; s += 4) {
        float t  = fmaf(range, fmaf((float)s, 1.f/128.f, 0.05f), t0);
        float px = fminf(fmaxf(fmaf(t, dx, ox), 0.f), 126.9999f);
        float py = fminf(fmaxf(fmaf(t, dy, oy), 0.f), 126.9999f);
        float pz = fminf(fmaxf(fmaf(t, dz, oz), 0.f), 126.9999f);

        float fx0 = floorf(px), fy0 = floorf(py), fz0 = floorf(pz);
        int ix0 = (int)fx0, iy0 = (int)fy0, iz0 = (int)fz0;
        float fx = px - fx0, fy = py - fy0, fz = pz - fz0;
        int ix1 = min(ix0 + 1, GD - 1);
        int iy1 = min(iy0 + 1, GD - 1);
        int iz1 = min(iz0 + 1, GD - 1);

        int a0 = ix0 << 14, a1 = ix1 << 14;   // ix * 128 * 128
        int b0 = iy0 << 7,  b1 = iy1 << 7;    // iy * 128

        float gx0 = 1.f - fx, gy0 = 1.f - fy, gz0 = 1.f - fz;

        int vox[8];
        vox[0] = a0 + b0 + iz0;  vox[1] = a0 + b0 + iz1;
        vox[2] = a0 + b1 + iz0;  vox[3] = a0 + b1 + iz1;
        vox[4] = a1 + b0 + iz0;  vox[5] = a1 + b0 + iz1;
        vox[6] = a1 + b1 + iz0;  vox[7] = a1 + b1 + iz1;

        float cw[8];
        cw[0] = gx0*gy0*gz0;  cw[1] = gx0*gy0*fz;
        cw[2] = gx0*fy *gz0;  cw[3] = gx0*fy *fz;
        cw[4] = fx *gy0*gz0;  cw[5] = fx *gy0*fz;
        cw[6] = fx *fy *gz0;  cw[7] = fx *fy *fz;

        float acc = 0.f;
        if (lane < 27) {
            #pragma unroll
            for (int k = 0; k < 8; k++)
                acc = fmaf(cw[k], __ldg(&grid[(long long)vox[k]*NCH + lane]), acc);
        } else if (lane == 27) {
            #pragma unroll
            for (int k = 0; k < 8; k++)
                acc = fmaf(cw[k], __ldg(&opacity[vox[k]]), acc);
        }
        if (lane < 28)
            coef[s][lane] = acc * mysh;
    }
    __syncthreads();

    // ---- phase 2: thread-per-sample dot + transmittance scan + reduce ----
    float dts = 0.f;
    float c0 = 0.f, c1 = 0.f, c2 = 0.f;
    if (tid < S_USED) {
        const float* row = coef[tid];
        #pragma unroll
        for (int j = 0; j < 9; j++) {
            c0 += row[j];
            c1 += row[9 + j];
            c2 += row[18 + j];
        }
        float op = fminf(fmaxf(row[27], 0.f), 100000.f);
        float delta = range * (1.f / 128.f);
        dts = -delta * op;
    }

    // inclusive warp scan of dts
    float xs = dts;
    #pragma unroll
    for (int off = 1; off < 32; off <<= 1) {
        float n = __shfl_up_sync(0xffffffffu, xs, off);
        if (lane >= off) xs += n;
    }
    if (lane == 31) wsum[warp] = xs;
    __syncthreads();
    float offacc = 0.f;
    #pragma unroll
    for (int w = 0; w < 4; w++)
        if (w < warp) offacc += wsum[w];
    float cum = offacc + xs - dts;     // exclusive prefix

    float r0 = 0.f, r1 = 0.f, r2 = 0.f;
    if (tid < S_USED) {
        float wgt = expf(cum) * (1.f - expf(dts));
        c0 = fminf(fmaxf(c0 + 0.5f, 0.f), 100000.f);
        c1 = fminf(fmaxf(c1 + 0.5f, 0.f), 100000.f);
        c2 = fminf(fmaxf(c2 + 0.5f, 0.f), 100000.f);
        r0 = wgt * c0;  r1 = wgt * c1;  r2 = wgt * c2;
    }

    #pragma unroll
    for (int off = 16; off > 0; off >>= 1) {
        r0 += __shfl_down_sync(0xffffffffu, r0, off);
        r1 += __shfl_down_sync(0xffffffffu, r1, off);
        r2 += __shfl_down_sync(0xffffffffu, r2, off);
    }
    if (lane == 0) {
        red[warp][0] = r0;  red[warp][1] = r1;  red[warp][2] = r2;
    }
    __syncthreads();
    if (tid == 0) {
        out[ray*3+0] = red[0][0] + red[1][0] + red[2][0] + red[3][0];
        out[ray*3+1] = red[0][1] + red[1][1] + red[2][1] + red[3][1];
        out[ray*3+2] = red[0][2] + red[1][2] + red[2][2] + red[3][2];
    }
}

extern "C" void kernel_launch(void* const* d_in, const int* in_sizes, int n_in,
                              void* d_out, int out_size)
{
    const float* x       = (const float*)d_in[0];
    const float* d       = (const float*)d_in[1];
    const float* tmin    = (const float*)d_in[2];
    const float* tmax    = (const float*)d_in[3];
    const float* grid    = (const float*)d_in[4];
    const float* opacity = (const float*)d_in[5];
    float* out = (float*)d_out;

    rf_render_kernel<<<N_RAYS, 128>>>(x, d, tmin, tmax, grid, opacity, out);
}

// round 2
// speedup vs baseline: 1.6365x; 1.6365x over previous
#include <cuda_runtime.h>
#include <math.h>

#define N_RAYS   32768
#define S_USED   115        // only samples 0..114 contribute
#define GD       128
#define NCH      27

__global__ __launch_bounds__(128, 8)
void rf_render_kernel(const float* __restrict__ xin,
                      const float* __restrict__ din,
                      const float* __restrict__ tminp,
                      const float* __restrict__ tmaxp,
                      const float* __restrict__ grid,
                      const float* __restrict__ opacity,
                      float* __restrict__ out)
{
    __shared__ float coef[S_USED][29];
    __shared__ float shs[9];
    __shared__ float wsum[4];
    __shared__ float red[4][3];

    const int ray  = blockIdx.x;
    const int tid  = threadIdx.x;
    const int lane = tid & 31;
    const int warp = tid >> 5;

    const float dx = din[ray*3+0];
    const float dy = din[ray*3+1];
    const float dz = din[ray*3+2];
    const float ox = xin[ray*3+0];
    const float oy = xin[ray*3+1];
    const float oz = xin[ray*3+2];
    const float t0 = tminp[ray];
    const float t1 = tmaxp[ray];
    const float range = t1 - t0;

    if (tid < 9) {
        float v = 0.f;
        switch (tid) {
            case 0: v = 0.28209479177387814f; break;
            case 1: v = -0.4886025119029199f * dy; break;
            case 2: v =  0.4886025119029199f * dz; break;
            case 3: v = -0.4886025119029199f * dx; break;
            case 4: v =  1.0925484305920792f * dx * dy; break;
            case 5: v = -1.0925484305920792f * dy * dz; break;
            case 6: v =  0.31539156525252005f * (2.f*dz*dz - dx*dx - dy*dy); break;
            case 7: v = -1.0925484305920792f * dx * dz; break;
            case 8: v =  0.5462742152960396f * (dx*dx - dy*dy); break;
        }
        shs[tid] = v;
    }
    __syncthreads();

    const float mysh = (lane < 27) ? shs[lane % 9] : 1.f;

    // Unified per-lane gather target: lanes 0..26 -> grid channel `lane`,
    // lanes 27..31 -> opacity (28..31 duplicate lane 27, result discarded).
    const float* bptr  = (lane < NCH) ? (grid + lane) : opacity;
    const int   stride = (lane < NCH) ? NCH : 1;

    // corner offsets: vox deltas {0,1,128,129,16384,16385,16512,16513} * stride
    const float* p[8];
    {
        int s1 = stride;
        int s128 = stride << 7;
        int s16384 = stride << 14;
        p[0] = bptr;
        p[1] = bptr + s1;
        p[2] = bptr + s128;
        p[3] = bptr + s128 + s1;
        p[4] = bptr + s16384;
        p[5] = bptr + s16384 + s1;
        p[6] = bptr + s16384 + s128;
        p[7] = bptr + s16384 + s128 + s1;
    }

    // ---- phase 1: warp-per-sample trilerp gather (channel-coalesced) ----
    for (int s = warp; s < S_USED; s += 4) {
        float t  = fmaf(range, fmaf((float)s, 1.f/128.f, 0.05f), t0);
        float px = fminf(fmaxf(fmaf(t, dx, ox), 0.f), 126.9999f);
        float py = fminf(fmaxf(fmaf(t, dy, oy), 0.f), 126.9999f);
        float pz = fminf(fmaxf(fmaf(t, dz, oz), 0.f), 126.9999f);

        float fx0 = floorf(px), fy0 = floorf(py), fz0 = floorf(pz);
        int ix0 = (int)fx0, iy0 = (int)fy0, iz0 = (int)fz0;
        float fx = px - fx0, fy = py - fy0, fz = pz - fz0;

        // base voxel index scaled by per-lane stride (32-bit safe: < 56.6M)
        int b = ((ix0 << 14) + (iy0 << 7) + iz0) * stride;

        float gx0 = 1.f - fx, gy0 = 1.f - fy, gz0 = 1.f - fz;

        float cw[8];
        cw[0] = gx0*gy0*gz0;  cw[1] = gx0*gy0*fz;
        cw[2] = gx0*fy *gz0;  cw[3] = gx0*fy *fz;
        cw[4] = fx *gy0*gz0;  cw[5] = fx *gy0*fz;
        cw[6] = fx *fy *gz0;  cw[7] = fx *fy *fz;

        float acc = 0.f;
        #pragma unroll
        for (int k = 0; k < 8; k++)
            acc = fmaf(cw[k], __ldg(p[k] + b), acc);

        if (lane < 28)
            coef[s][lane] = acc * mysh;
    }
    __syncthreads();

    // ---- phase 2: thread-per-sample dot + transmittance scan + reduce ----
    float dts = 0.f;
    float c0 = 0.f, c1 = 0.f, c2 = 0.f;
    if (tid < S_USED) {
        const float* row = coef[tid];
        #pragma unroll
        for (int j = 0; j < 9; j++) {
            c0 += row[j];
            c1 += row[9 + j];
            c2 += row[18 + j];
        }
        float op = fminf(fmaxf(row[27], 0.f), 100000.f);
        float delta = range * (1.f / 128.f);
        dts = -delta * op;
    }

    float xs = dts;
    #pragma unroll
    for (int off = 1; off < 32; off <<= 1) {
        float n = __shfl_up_sync(0xffffffffu, xs, off);
        if (lane >= off) xs += n;
    }
    if (lane == 31) wsum[warp] = xs;
    __syncthreads();
    float offacc = 0.f;
    #pragma unroll
    for (int w = 0; w < 4; w++)
        if (w < warp) offacc += wsum[w];
    float cum = offacc + xs - dts;     // exclusive prefix

    float r0 = 0.f, r1 = 0.f, r2 = 0.f;
    if (tid < S_USED) {
        float wgt = expf(cum) * (1.f - expf(dts));
        c0 = fminf(fmaxf(c0 + 0.5f, 0.f), 100000.f);
        c1 = fminf(fmaxf(c1 + 0.5f, 0.f), 100000.f);
        c2 = fminf(fmaxf(c2 + 0.5f, 0.f), 100000.f);
        r0 = wgt * c0;  r1 = wgt * c1;  r2 = wgt * c2;
    }

    #pragma unroll
    for (int off = 16; off > 0; off >>= 1) {
        r0 += __shfl_down_sync(0xffffffffu, r0, off);
        r1 += __shfl_down_sync(0xffffffffu, r1, off);
        r2 += __shfl_down_sync(0xffffffffu, r2, off);
    }
    if (lane == 0) {
        red[warp][0] = r0;  red[warp][1] = r1;  red[warp][2] = r2;
    }
    __syncthreads();
    if (tid == 0) {
        out[ray*3+0] = red[0][0] + red[1][0] + red[2][0] + red[3][0];
        out[ray*3+1] = red[0][1] + red[1][1] + red[2][1] + red[3][1];
        out[ray*3+2] = red[0][2] + red[1][2] + red[2][2] + red[3][2];
    }
}

extern "C" void kernel_launch(void* const* d_in, const int* in_sizes, int n_in,
                              void* d_out, int out_size)
{
    const float* x       = (const float*)d_in[0];
    const float* d       = (const float*)d_in[1];
    const float* tmin    = (const float*)d_in[2];
    const float* tmax    = (const float*)d_in[3];
    const float* grid    = (const float*)d_in[4];
    const float* opacity = (const float*)d_in[5];
    float* out = (float*)d_out;

    rf_render_kernel<<<N_RAYS, 128>>>(x, d, tmin, tmax, grid, opacity, out);
}

// round 3
// speedup vs baseline: 1.7662x; 1.0793x over previous
#include <cuda_runtime.h>
#include <math.h>

#define N_RAYS   32768
#define S_USED   115        // only samples 0..114 contribute
#define GD       128
#define NCH      27

struct RayCtx {
    float ox, oy, oz, dx, dy, dz, t0, range;
};

// compute scaled base index + 8 corner weights for sample s
__device__ __forceinline__ void sample_setup(const RayCtx& rc, int s, int stride,
                                             int& b, float cw[8])
{
    float t  = fmaf(rc.range, fmaf((float)s, 1.f/128.f, 0.05f), rc.t0);
    float px = fminf(fmaxf(fmaf(t, rc.dx, rc.ox), 0.f), 126.9999f);
    float py = fminf(fmaxf(fmaf(t, rc.dy, rc.oy), 0.f), 126.9999f);
    float pz = fminf(fmaxf(fmaf(t, rc.dz, rc.oz), 0.f), 126.9999f);

    float fx0 = floorf(px), fy0 = floorf(py), fz0 = floorf(pz);
    int ix0 = (int)fx0, iy0 = (int)fy0, iz0 = (int)fz0;
    float fx = px - fx0, fy = py - fy0, fz = pz - fz0;

    b = ((ix0 << 14) + (iy0 << 7) + iz0) * stride;

    float gx0 = 1.f - fx, gy0 = 1.f - fy, gz0 = 1.f - fz;
    cw[0] = gx0*gy0*gz0;  cw[1] = gx0*gy0*fz;
    cw[2] = gx0*fy *gz0;  cw[3] = gx0*fy *fz;
    cw[4] = fx *gy0*gz0;  cw[5] = fx *gy0*fz;
    cw[6] = fx *fy *gz0;  cw[7] = fx *fy *fz;
}

__global__ __launch_bounds__(128, 6)
void rf_render_kernel(const float* __restrict__ xin,
                      const float* __restrict__ din,
                      const float* __restrict__ tminp,
                      const float* __restrict__ tmaxp,
                      const float* __restrict__ grid,
                      const float* __restrict__ opacity,
                      float* __restrict__ out)
{
    __shared__ float coef[S_USED][29];
    __shared__ float shs[9];
    __shared__ float wsum[4];
    __shared__ float red[4][3];

    const int ray  = blockIdx.x;
    const int tid  = threadIdx.x;
    const int lane = tid & 31;
    const int warp = tid >> 5;

    RayCtx rc;
    rc.dx = din[ray*3+0];
    rc.dy = din[ray*3+1];
    rc.dz = din[ray*3+2];
    rc.ox = xin[ray*3+0];
    rc.oy = xin[ray*3+1];
    rc.oz = xin[ray*3+2];
    rc.t0 = tminp[ray];
    rc.range = tmaxp[ray] - rc.t0;

    if (tid < 9) {
        float v = 0.f;
        switch (tid) {
            case 0: v = 0.28209479177387814f; break;
            case 1: v = -0.4886025119029199f * rc.dy; break;
            case 2: v =  0.4886025119029199f * rc.dz; break;
            case 3: v = -0.4886025119029199f * rc.dx; break;
            case 4: v =  1.0925484305920792f * rc.dx * rc.dy; break;
            case 5: v = -1.0925484305920792f * rc.dy * rc.dz; break;
            case 6: v =  0.31539156525252005f * (2.f*rc.dz*rc.dz - rc.dx*rc.dx - rc.dy*rc.dy); break;
            case 7: v = -1.0925484305920792f * rc.dx * rc.dz; break;
            case 8: v =  0.5462742152960396f * (rc.dx*rc.dx - rc.dy*rc.dy); break;
        }
        shs[tid] = v;
    }
    __syncthreads();

    const float mysh = (lane < 27) ? shs[lane % 9] : 1.f;

    // lanes 0..26 -> grid channel `lane`; lanes 27..31 -> opacity (dupes discarded)
    const float* bptr  = (lane < NCH) ? (grid + lane) : opacity;
    const int   stride = (lane < NCH) ? NCH : 1;

    const float* p[8];
    {
        int s1 = stride;
        int s128 = stride << 7;
        int s16384 = stride << 14;
        p[0] = bptr;
        p[1] = bptr + s1;
        p[2] = bptr + s128;
        p[3] = bptr + s128 + s1;
        p[4] = bptr + s16384;
        p[5] = bptr + s16384 + s1;
        p[6] = bptr + s16384 + s128;
        p[7] = bptr + s16384 + s128 + s1;
    }

    // ---- phase 1: warp-per-sample gather, 2 samples in flight per iter ----
    int s = warp;
    for (; s + 4 < S_USED; s += 8) {
        int bA, bB;
        float cwA[8], cwB[8];
        sample_setup(rc, s,     stride, bA, cwA);
        sample_setup(rc, s + 4, stride, bB, cwB);

        float vA[8], vB[8];
        #pragma unroll
        for (int k = 0; k < 8; k++) vA[k] = __ldg(p[k] + bA);
        #pragma unroll
        for (int k = 0; k < 8; k++) vB[k] = __ldg(p[k] + bB);

        float accA = 0.f, accB = 0.f;
        #pragma unroll
        for (int k = 0; k < 8; k++) accA = fmaf(cwA[k], vA[k], accA);
        #pragma unroll
        for (int k = 0; k < 8; k++) accB = fmaf(cwB[k], vB[k], accB);

        if (lane < 28) {
            coef[s][lane]     = accA * mysh;
            coef[s + 4][lane] = accB * mysh;
        }
    }
    if (s < S_USED) {
        int b;
        float cw[8];
        sample_setup(rc, s, stride, b, cw);
        float v[8];
        #pragma unroll
        for (int k = 0; k < 8; k++) v[k] = __ldg(p[k] + b);
        float acc = 0.f;
        #pragma unroll
        for (int k = 0; k < 8; k++) acc = fmaf(cw[k], v[k], acc);
        if (lane < 28)
            coef[s][lane] = acc * mysh;
    }
    __syncthreads();

    // ---- phase 2: thread-per-sample dot + transmittance scan + reduce ----
    float dts = 0.f;
    float c0 = 0.f, c1 = 0.f, c2 = 0.f;
    if (tid < S_USED) {
        const float* row = coef[tid];
        #pragma unroll
        for (int j = 0; j < 9; j++) {
            c0 += row[j];
            c1 += row[9 + j];
            c2 += row[18 + j];
        }
        float op = fminf(fmaxf(row[27], 0.f), 100000.f);
        float delta = rc.range * (1.f / 128.f);
        dts = -delta * op;
    }

    float xs = dts;
    #pragma unroll
    for (int off = 1; off < 32; off <<= 1) {
        float n = __shfl_up_sync(0xffffffffu, xs, off);
        if (lane >= off) xs += n;
    }
    if (lane == 31) wsum[warp] = xs;
    __syncthreads();
    float offacc = 0.f;
    #pragma unroll
    for (int w = 0; w < 4; w++)
        if (w < warp) offacc += wsum[w];
    float cum = offacc + xs - dts;     // exclusive prefix

    float r0 = 0.f, r1 = 0.f, r2 = 0.f;
    if (tid < S_USED) {
        float wgt = expf(cum) * (1.f - expf(dts));
        c0 = fminf(fmaxf(c0 + 0.5f, 0.f), 100000.f);
        c1 = fminf(fmaxf(c1 + 0.5f, 0.f), 100000.f);
        c2 = fminf(fmaxf(c2 + 0.5f, 0.f), 100000.f);
        r0 = wgt * c0;  r1 = wgt * c1;  r2 = wgt * c2;
    }

    #pragma unroll
    for (int off = 16; off > 0; off >>= 1) {
        r0 += __shfl_down_sync(0xffffffffu, r0, off);
        r1 += __shfl_down_sync(0xffffffffu, r1, off);
        r2 += __shfl_down_sync(0xffffffffu, r2, off);
    }
    if (lane == 0) {
        red[warp][0] = r0;  red[warp][1] = r1;  red[warp][2] = r2;
    }
    __syncthreads();
    if (tid == 0) {
        out[ray*3+0] = red[0][0] + red[1][0] + red[2][0] + red[3][0];
        out[ray*3+1] = red[0][1] + red[1][1] + red[2][1] + red[3][1];
        out[ray*3+2] = red[0][2] + red[1][2] + red[2][2] + red[3][2];
    }
}

extern "C" void kernel_launch(void* const* d_in, const int* in_sizes, int n_in,
                              void* d_out, int out_size)
{
    const float* x       = (const float*)d_in[0];
    const float* d       = (const float*)d_in[1];
    const float* tmin    = (const float*)d_in[2];
    const float* tmax    = (const float*)d_in[3];
    const float* grid    = (const float*)d_in[4];
    const float* opacity = (const float*)d_in[5];
    float* out = (float*)d_out;

    rf_render_kernel<<<N_RAYS, 128>>>(x, d, tmin, tmax, grid, opacity, out);
}